// round 3
// baseline (speedup 1.0000x reference)
#include <cuda_runtime.h>
#include <cstdint>
#include <math.h>

// Problem constants (fixed by setup_inputs)
#define S_LEN  2048
#define DMODEL 4096
#define HQ     32
#define HKV    8
#define HD     128
#define DKV    (HKV * HD)   // 1024

// ---------------------------------------------------------------------------
// Scratch (device globals; no allocations allowed in kernel_launch)
// ---------------------------------------------------------------------------
__device__ float g_q[(size_t)S_LEN * DMODEL];               //  33.5 MB
__device__ float g_k[(size_t)S_LEN * DKV];                  //   8.4 MB
__device__ float g_v[(size_t)S_LEN * DKV];                  //   8.4 MB
__device__ float g_attn[(size_t)S_LEN * DMODEL];            //  33.5 MB
__device__ float g_scores[(size_t)HQ * S_LEN * S_LEN];      // 536   MB

#define SPITCH 132   // 128 + 4 padding floats; rows stay 16B-aligned

// ---------------------------------------------------------------------------
// GEMM NT:  C[M,N] = alpha * A[M,K] * B[N,K]^T   (row-major, K contiguous)
// Used for: Q/K/V projections and final O-projection. (Exonerated stages.)
// ---------------------------------------------------------------------------
__global__ __launch_bounds__(256) void gemm_nt(
    const float* __restrict__ A, const float* __restrict__ B, float* __restrict__ C,
    int M, int N, int K, int lda, int ldb, int ldc,
    long long strA, long long strB, long long strC, int bdivB, float alpha)
{
    __shared__ __align__(16) float As[16 * SPITCH];
    __shared__ __align__(16) float Bs[16 * SPITCH];

    A += (long long)blockIdx.z * strA;
    B += (long long)(blockIdx.z / bdivB) * strB;
    C += (long long)blockIdx.z * strC;

    const int row0 = blockIdx.y * 128;
    const int col0 = blockIdx.x * 128;
    const int tid  = threadIdx.x;
    const int tn   = tid & 15;
    const int tm   = tid >> 4;

    float acc[8][8];
#pragma unroll
    for (int i = 0; i < 8; i++)
#pragma unroll
        for (int j = 0; j < 8; j++) acc[i][j] = 0.f;

    for (int k0 = 0; k0 < K; k0 += 16) {
#pragma unroll
        for (int it = 0; it < 2; it++) {
            int f = tid + 256 * it;
            int r = f >> 2;
            int c4 = (f & 3) << 2;
            float4 v = *(const float4*)(A + (long long)(row0 + r) * lda + k0 + c4);
            As[(c4 + 0) * SPITCH + r] = v.x;
            As[(c4 + 1) * SPITCH + r] = v.y;
            As[(c4 + 2) * SPITCH + r] = v.z;
            As[(c4 + 3) * SPITCH + r] = v.w;
        }
#pragma unroll
        for (int it = 0; it < 2; it++) {
            int f = tid + 256 * it;
            int r = f >> 2;
            int c4 = (f & 3) << 2;
            float4 v = *(const float4*)(B + (long long)(col0 + r) * ldb + k0 + c4);
            Bs[(c4 + 0) * SPITCH + r] = v.x;
            Bs[(c4 + 1) * SPITCH + r] = v.y;
            Bs[(c4 + 2) * SPITCH + r] = v.z;
            Bs[(c4 + 3) * SPITCH + r] = v.w;
        }
        __syncthreads();

#pragma unroll
        for (int k = 0; k < 16; k++) {
            const float* Ak = As + k * SPITCH;
            const float* Bk = Bs + k * SPITCH;
            float a[8], b[8];
            *(float4*)(a)     = *(const float4*)(Ak + tm * 4);
            *(float4*)(a + 4) = *(const float4*)(Ak + 64 + tm * 4);
            *(float4*)(b)     = *(const float4*)(Bk + tn * 4);
            *(float4*)(b + 4) = *(const float4*)(Bk + 64 + tn * 4);
#pragma unroll
            for (int i = 0; i < 8; i++)
#pragma unroll
                for (int j = 0; j < 8; j++)
                    acc[i][j] = fmaf(a[i], b[j], acc[i][j]);
        }
        __syncthreads();
    }

#pragma unroll
    for (int i = 0; i < 8; i++) {
        int r = row0 + ((i < 4) ? (tm * 4 + i) : (64 + tm * 4 + (i - 4)));
        float* crow = C + (long long)r * ldc + col0;
        float4 v0 = make_float4(acc[i][0] * alpha, acc[i][1] * alpha,
                                acc[i][2] * alpha, acc[i][3] * alpha);
        float4 v1 = make_float4(acc[i][4] * alpha, acc[i][5] * alpha,
                                acc[i][6] * alpha, acc[i][7] * alpha);
        *(float4*)(crow + tn * 4)      = v0;
        *(float4*)(crow + 64 + tn * 4) = v1;
    }
}

// ---------------------------------------------------------------------------
// GEMM NN:  C[M,N] = alpha * A[M,K] * B[K,N]   (row-major) — PV stage.
// ---------------------------------------------------------------------------
__global__ __launch_bounds__(256) void gemm_nn(
    const float* __restrict__ A, const float* __restrict__ B, float* __restrict__ C,
    int M, int N, int K, int lda, int ldb, int ldc,
    long long strA, long long strB, long long strC, int bdivB, float alpha)
{
    __shared__ __align__(16) float As[16 * SPITCH];
    __shared__ __align__(16) float Bs[16 * SPITCH];

    A += (long long)blockIdx.z * strA;
    B += (long long)(blockIdx.z / bdivB) * strB;
    C += (long long)blockIdx.z * strC;

    const int row0 = blockIdx.y * 128;
    const int col0 = blockIdx.x * 128;
    const int tid  = threadIdx.x;
    const int tn   = tid & 15;
    const int tm   = tid >> 4;

    float acc[8][8];
#pragma unroll
    for (int i = 0; i < 8; i++)
#pragma unroll
        for (int j = 0; j < 8; j++) acc[i][j] = 0.f;

    for (int k0 = 0; k0 < K; k0 += 16) {
#pragma unroll
        for (int it = 0; it < 2; it++) {
            int f = tid + 256 * it;
            int r = f >> 2;
            int c4 = (f & 3) << 2;
            float4 v = *(const float4*)(A + (long long)(row0 + r) * lda + k0 + c4);
            As[(c4 + 0) * SPITCH + r] = v.x;
            As[(c4 + 1) * SPITCH + r] = v.y;
            As[(c4 + 2) * SPITCH + r] = v.z;
            As[(c4 + 3) * SPITCH + r] = v.w;
        }
#pragma unroll
        for (int it = 0; it < 2; it++) {
            int f = tid + 256 * it;
            int r = f >> 5;            // 0..15
            int c4 = (f & 31) << 2;    // 0..124
            float4 v = *(const float4*)(B + (long long)(k0 + r) * ldb + col0 + c4);
            *(float4*)(Bs + r * SPITCH + c4) = v;
        }
        __syncthreads();

#pragma unroll
        for (int k = 0; k < 16; k++) {
            const float* Ak = As + k * SPITCH;
            const float* Bk = Bs + k * SPITCH;
            float a[8], b[8];
            *(float4*)(a)     = *(const float4*)(Ak + tm * 4);
            *(float4*)(a + 4) = *(const float4*)(Ak + 64 + tm * 4);
            *(float4*)(b)     = *(const float4*)(Bk + tn * 4);
            *(float4*)(b + 4) = *(const float4*)(Bk + 64 + tn * 4);
#pragma unroll
            for (int i = 0; i < 8; i++)
#pragma unroll
                for (int j = 0; j < 8; j++)
                    acc[i][j] = fmaf(a[i], b[j], acc[i][j]);
        }
        __syncthreads();
    }

#pragma unroll
    for (int i = 0; i < 8; i++) {
        int r = row0 + ((i < 4) ? (tm * 4 + i) : (64 + tm * 4 + (i - 4)));
        float* crow = C + (long long)r * ldc + col0;
        float4 v0 = make_float4(acc[i][0] * alpha, acc[i][1] * alpha,
                                acc[i][2] * alpha, acc[i][3] * alpha);
        float4 v1 = make_float4(acc[i][4] * alpha, acc[i][5] * alpha,
                                acc[i][6] * alpha, acc[i][7] * alpha);
        *(float4*)(crow + tn * 4)      = v0;
        *(float4*)(crow + 64 + tn * 4) = v1;
    }
}

// ---------------------------------------------------------------------------
// RoPE v2 (fresh implementation): div/mod indexing, double-precision trig.
// x[2i]   <- x[2i]*cos - x[2i+1]*sin
// x[2i+1] <- x[2i]*sin + x[2i+1]*cos,  angle = s * 10000^(-2i/128)
// ---------------------------------------------------------------------------
__global__ void rope_v2() {
    long long idx = (long long)blockIdx.x * blockDim.x + threadIdx.x;
    const long long QP = (long long)S_LEN * HQ * 64;
    const long long KP = (long long)S_LEN * HKV * 64;
    if (idx >= QP + KP) return;

    float* base; int s, h, i, stride;
    if (idx < QP) {
        s = (int)(idx / (HQ * 64));
        int rem = (int)(idx % (HQ * 64));
        h = rem / 64; i = rem % 64;
        base = g_q; stride = DMODEL;
    } else {
        long long t = idx - QP;
        s = (int)(t / (HKV * 64));
        int rem = (int)(t % (HKV * 64));
        h = rem / 64; i = rem % 64;
        base = g_k; stride = DKV;
    }

    float invf = (float)(1.0 / pow(10000.0, (double)i / 64.0));
    float ang = (float)s * invf;           // fp32 product, like reference
    double sd, cd;
    sincos((double)ang, &sd, &cd);         // accurate trig of that fp32 angle
    float c = (float)cd, sn = (float)sd;

    size_t off = (size_t)s * (size_t)stride + (size_t)h * HD + 2 * (size_t)i;
    float x1 = base[off], x2 = base[off + 1];
    base[off]     = x1 * c  - x2 * sn;
    base[off + 1] = x1 * sn + x2 * c;
}

// ---------------------------------------------------------------------------
// Scores v2 (fresh implementation):
//   scores[h][q][k] = scale * dot(Q[q, h*128:...], K[k, (h/4)*128:...])
// Block: 256 threads = 8 warps. Warp w owns q-row (q0+w); lane l owns k-row
// (k0+l). Padded smem rows (129) -> conflict-free Ks[l][d] access.
// Grid: (S/32, S/8, HQ).
// ---------------------------------------------------------------------------
__global__ __launch_bounds__(256) void scores_v2() {
    __shared__ float Ks[32][129];
    __shared__ __align__(16) float Qs[8][128];

    const int h   = blockIdx.z;
    const int kvh = h >> 2;           // GQA: q head h -> kv head h/4
    const int k0  = blockIdx.x * 32;
    const int q0  = blockIdx.y * 8;
    const int tid = threadIdx.x;

    // K tile: 32 rows x 128 floats
#pragma unroll
    for (int it = 0; it < 4; it++) {
        int f = tid + 256 * it;       // 0..1023
        int r = f >> 5;               // 0..31
        int c = (f & 31) * 4;         // 0..124
        float4 v = *(const float4*)(g_k + (size_t)(k0 + r) * DKV + kvh * HD + c);
        Ks[r][c] = v.x; Ks[r][c + 1] = v.y; Ks[r][c + 2] = v.z; Ks[r][c + 3] = v.w;
    }
    // Q tile: 8 rows x 128 floats
    {
        int r = tid >> 5;             // 0..7
        int c = (tid & 31) * 4;       // 0..124
        float4 v = *(const float4*)(g_q + (size_t)(q0 + r) * DMODEL + h * HD + c);
        *(float4*)&Qs[r][c] = v;
    }
    __syncthreads();

    const int w = tid >> 5, l = tid & 31;
    float acc = 0.f;
#pragma unroll 8
    for (int d = 0; d < 128; d++)
        acc = fmaf(Qs[w][d], Ks[l][d], acc);

    g_scores[(size_t)h * S_LEN * S_LEN + (size_t)(q0 + w) * S_LEN + (k0 + l)]
        = acc * 0.08838834764831845f;   // 1/sqrt(128)
}

// ---------------------------------------------------------------------------
// Softmax v2 (fresh implementation): one warp per row, shuffle reductions.
// Grid: (HQ*S)/8 blocks of 256 threads (8 warps).
// ---------------------------------------------------------------------------
__global__ __launch_bounds__(256) void softmax_v2() {
    const int row = blockIdx.x * 8 + (threadIdx.x >> 5);
    const int l   = threadIdx.x & 31;
    float* p = g_scores + (size_t)row * S_LEN;

    float vals[64];
    float m = -3.0e38f;
#pragma unroll
    for (int i = 0; i < 64; i++) {
        vals[i] = p[l + 32 * i];
        m = fmaxf(m, vals[i]);
    }
#pragma unroll
    for (int o = 16; o > 0; o >>= 1)
        m = fmaxf(m, __shfl_xor_sync(0xffffffffu, m, o));

    float s = 0.f;
#pragma unroll
    for (int i = 0; i < 64; i++) {
        vals[i] = expf(vals[i] - m);
        s += vals[i];
    }
#pragma unroll
    for (int o = 16; o > 0; o >>= 1)
        s += __shfl_xor_sync(0xffffffffu, s, o);

    float inv = 1.0f / s;
#pragma unroll
    for (int i = 0; i < 64; i++)
        p[l + 32 * i] = vals[i] * inv;
}

// ---------------------------------------------------------------------------
// Launch
// ---------------------------------------------------------------------------
extern "C" void kernel_launch(void* const* d_in, const int* in_sizes, int n_in,
                              void* d_out, int out_size)
{
    const float* x  = (const float*)d_in[0];
    const float* wq = (const float*)d_in[1];
    const float* wk = (const float*)d_in[2];
    const float* wv = (const float*)d_in[3];
    const float* wo = (const float*)d_in[4];
    float* out = (float*)d_out;

    float *q, *k, *v, *attn, *sc;
    cudaGetSymbolAddress((void**)&q,    g_q);
    cudaGetSymbolAddress((void**)&k,    g_k);
    cudaGetSymbolAddress((void**)&v,    g_v);
    cudaGetSymbolAddress((void**)&attn, g_attn);
    cudaGetSymbolAddress((void**)&sc,   g_scores);

    // 1) Projections: Q = x*wq^T, K = x*wk^T, V = x*wv^T
    gemm_nt<<<dim3(DMODEL / 128, S_LEN / 128, 1), 256>>>(
        x, wq, q, S_LEN, DMODEL, DMODEL, DMODEL, DMODEL, DMODEL, 0, 0, 0, 1, 1.0f);
    gemm_nt<<<dim3(DKV / 128, S_LEN / 128, 1), 256>>>(
        x, wk, k, S_LEN, DKV, DMODEL, DMODEL, DMODEL, DKV, 0, 0, 0, 1, 1.0f);
    gemm_nt<<<dim3(DKV / 128, S_LEN / 128, 1), 256>>>(
        x, wv, v, S_LEN, DKV, DMODEL, DMODEL, DMODEL, DKV, 0, 0, 0, 1, 1.0f);

    // 2) RoPE in-place on Q and K
    {
        long long total = (long long)S_LEN * HQ * 64 + (long long)S_LEN * HKV * 64;
        rope_v2<<<(int)((total + 255) / 256), 256>>>();
    }

    // 3) scores[h] = scale * Q_h * K_{h/4}^T  (fresh kernel)
    scores_v2<<<dim3(S_LEN / 32, S_LEN / 8, HQ), 256>>>();

    // 4) softmax over rows (fresh kernel)
    softmax_v2<<<(HQ * S_LEN) / 8, 256>>>();

    // 5) attn[h] = P_h * V_{h/4}   (batched NN)
    gemm_nn<<<dim3(HD / 128, S_LEN / 128, HQ), 256>>>(
        sc, v, attn, S_LEN, HD, S_LEN, S_LEN, DKV, DMODEL,
        /*strA=*/(long long)S_LEN * S_LEN, /*strB=*/HD, /*strC=*/HD,
        /*bdivB=*/4, 1.0f);

    // 6) Output projection: out = attn * wo^T
    gemm_nt<<<dim3(DMODEL / 128, S_LEN / 128, 1), 256>>>(
        attn, wo, out, S_LEN, DMODEL, DMODEL, DMODEL, DMODEL, DMODEL,
        0, 0, 0, 1, 1.0f);
}

// round 4
// speedup vs baseline: 3.4079x; 3.4079x over previous
#include <cuda_runtime.h>
#include <cuda_bf16.h>
#include <cstdint>
#include <math.h>

// Problem constants (fixed by setup_inputs)
#define S_LEN  2048
#define DMODEL 4096
#define HQ     32
#define HKV    8
#define HD     128
#define DKV    (HKV * HD)   // 1024

// ---------------------------------------------------------------------------
// Scratch (device globals)
// ---------------------------------------------------------------------------
__device__ float g_q[(size_t)S_LEN * DMODEL];
__device__ float g_k[(size_t)S_LEN * DKV];
__device__ float g_v[(size_t)S_LEN * DKV];
__device__ float g_vt[(size_t)DKV * S_LEN];                 // V transposed [d][s]
__device__ float g_attn[(size_t)S_LEN * DMODEL];
__device__ float g_scores[(size_t)HQ * S_LEN * S_LEN];

// ---------------------------------------------------------------------------
// PTX helpers
// ---------------------------------------------------------------------------
__device__ __forceinline__ uint32_t smem_u32(const void* p) {
    uint32_t a;
    asm("{ .reg .u64 t; cvta.to.shared.u64 t, %1; cvt.u32.u64 %0, t; }"
        : "=r"(a) : "l"(p));
    return a;
}
__device__ __forceinline__ void ldsm_x4(uint32_t r[4], uint32_t addr) {
    asm volatile("ldmatrix.sync.aligned.m8n8.x4.shared.b16 {%0,%1,%2,%3}, [%4];"
        : "=r"(r[0]), "=r"(r[1]), "=r"(r[2]), "=r"(r[3]) : "r"(addr));
}
__device__ __forceinline__ void ldsm_x2(uint32_t r[2], uint32_t addr) {
    asm volatile("ldmatrix.sync.aligned.m8n8.x2.shared.b16 {%0,%1}, [%2];"
        : "=r"(r[0]), "=r"(r[1]) : "r"(addr));
}
__device__ __forceinline__ void mma_bf16(float d[4], const uint32_t a[4],
                                         const uint32_t b[2]) {
    asm volatile(
        "mma.sync.aligned.m16n8k16.row.col.f32.bf16.bf16.f32 "
        "{%0,%1,%2,%3}, {%4,%5,%6,%7}, {%8,%9}, {%0,%1,%2,%3};"
        : "+f"(d[0]), "+f"(d[1]), "+f"(d[2]), "+f"(d[3])
        : "r"(a[0]), "r"(a[1]), "r"(a[2]), "r"(a[3]), "r"(b[0]), "r"(b[1]));
}
__device__ __forceinline__ uint32_t pack_bf16(__nv_bfloat16 lo, __nv_bfloat16 hi) {
    __nv_bfloat162 t = __halves2bfloat162(lo, hi);
    return *reinterpret_cast<uint32_t*>(&t);
}

// ---------------------------------------------------------------------------
// Tensor-core GEMM NT, split-bf16 (hi/lo):
//   C[M,N] = alpha * A[M,K] * B[N,K]^T     (row-major, K contiguous)
// Tile 128x128, K-step 32, 256 threads (8 warps: 2 over M x 4 over N).
// Batched over blockIdx.z; B index = z / bdivB (GQA map).
// Requires: M,N % 128 == 0, K % 32 == 0, A/B rows 16B-aligned.
// ---------------------------------------------------------------------------
#define KSTEP 32
#define BPITCH 40          // smem pitch in bf16 elements (80 bytes)

__global__ __launch_bounds__(256) void tc_gemm_nt(
    const float* __restrict__ A, const float* __restrict__ B, float* __restrict__ C,
    int M, int N, int K, int lda, int ldb, int ldc,
    long long strA, long long strB, long long strC, int bdivB, float alpha)
{
    __shared__ __align__(16) __nv_bfloat16 Ah[128 * BPITCH];
    __shared__ __align__(16) __nv_bfloat16 Al[128 * BPITCH];
    __shared__ __align__(16) __nv_bfloat16 Bh[128 * BPITCH];
    __shared__ __align__(16) __nv_bfloat16 Bl[128 * BPITCH];

    A += (long long)blockIdx.z * strA;
    B += (long long)(blockIdx.z / bdivB) * strB;
    C += (long long)blockIdx.z * strC;

    const int row0 = blockIdx.y * 128;
    const int col0 = blockIdx.x * 128;
    const int tid  = threadIdx.x;
    const int lane = tid & 31;
    const int w    = tid >> 5;
    const int wm   = (w & 1) * 64;   // warp M offset
    const int wn   = (w >> 1) * 32;  // warp N offset

    const uint32_t ah0 = smem_u32(Ah);
    const uint32_t al0 = smem_u32(Al);
    const uint32_t bh0 = smem_u32(Bh);
    const uint32_t bl0 = smem_u32(Bl);

    float acc[4][4][4];
#pragma unroll
    for (int i = 0; i < 4; i++)
#pragma unroll
        for (int j = 0; j < 4; j++)
#pragma unroll
            for (int e = 0; e < 4; e++) acc[i][j][e] = 0.f;

    for (int k0 = 0; k0 < K; k0 += KSTEP) {
        // ---- load + convert A tile (128 x 32 floats) ----
#pragma unroll
        for (int it = 0; it < 4; it++) {
            int idx = tid + 256 * it;          // 0..1023
            int r   = idx >> 3;                // 0..127
            int c4  = (idx & 7) << 2;          // 0,4,...,28
            float4 v = *(const float4*)(A + (long long)(row0 + r) * lda + k0 + c4);
            __nv_bfloat16 h0 = __float2bfloat16(v.x);
            __nv_bfloat16 h1 = __float2bfloat16(v.y);
            __nv_bfloat16 h2 = __float2bfloat16(v.z);
            __nv_bfloat16 h3 = __float2bfloat16(v.w);
            __nv_bfloat16 l0 = __float2bfloat16(v.x - __bfloat162float(h0));
            __nv_bfloat16 l1 = __float2bfloat16(v.y - __bfloat162float(h1));
            __nv_bfloat16 l2 = __float2bfloat16(v.z - __bfloat162float(h2));
            __nv_bfloat16 l3 = __float2bfloat16(v.w - __bfloat162float(h3));
            uint32_t* ph = (uint32_t*)(Ah + r * BPITCH + c4);
            uint32_t* pl = (uint32_t*)(Al + r * BPITCH + c4);
            ph[0] = pack_bf16(h0, h1); ph[1] = pack_bf16(h2, h3);
            pl[0] = pack_bf16(l0, l1); pl[1] = pack_bf16(l2, l3);
        }
        // ---- load + convert B tile (128 x 32 floats) ----
#pragma unroll
        for (int it = 0; it < 4; it++) {
            int idx = tid + 256 * it;
            int r   = idx >> 3;
            int c4  = (idx & 7) << 2;
            float4 v = *(const float4*)(B + (long long)(col0 + r) * ldb + k0 + c4);
            __nv_bfloat16 h0 = __float2bfloat16(v.x);
            __nv_bfloat16 h1 = __float2bfloat16(v.y);
            __nv_bfloat16 h2 = __float2bfloat16(v.z);
            __nv_bfloat16 h3 = __float2bfloat16(v.w);
            __nv_bfloat16 l0 = __float2bfloat16(v.x - __bfloat162float(h0));
            __nv_bfloat16 l1 = __float2bfloat16(v.y - __bfloat162float(h1));
            __nv_bfloat16 l2 = __float2bfloat16(v.z - __bfloat162float(h2));
            __nv_bfloat16 l3 = __float2bfloat16(v.w - __bfloat162float(h3));
            uint32_t* ph = (uint32_t*)(Bh + r * BPITCH + c4);
            uint32_t* pl = (uint32_t*)(Bl + r * BPITCH + c4);
            ph[0] = pack_bf16(h0, h1); ph[1] = pack_bf16(h2, h3);
            pl[0] = pack_bf16(l0, l1); pl[1] = pack_bf16(l2, l3);
        }
        __syncthreads();

        // ---- compute: 2 k-chunks of 16 ----
#pragma unroll
        for (int kc = 0; kc < 2; kc++) {
            const int kb = kc * 16;
            uint32_t afh[4][4], afl[4][4], bfh[4][2], bfl[4][2];
            // A fragments: row = wm + mi*16 + (lane&15), col = kb + (lane>>4)*8
            {
                int rr = lane & 15;
                int cc = kb + ((lane >> 4) << 3);
#pragma unroll
                for (int mi = 0; mi < 4; mi++) {
                    uint32_t off = (uint32_t)((wm + mi * 16 + rr) * (BPITCH * 2) + cc * 2);
                    ldsm_x4(afh[mi], ah0 + off);
                    ldsm_x4(afl[mi], al0 + off);
                }
            }
            // B fragments: row = wn + nj*8 + (lane&7), col = kb + ((lane>>3)&1)*8
            {
                int rr = lane & 7;
                int cc = kb + (((lane >> 3) & 1) << 3);
#pragma unroll
                for (int nj = 0; nj < 4; nj++) {
                    uint32_t off = (uint32_t)((wn + nj * 8 + rr) * (BPITCH * 2) + cc * 2);
                    ldsm_x2(bfh[nj], bh0 + off);
                    ldsm_x2(bfl[nj], bl0 + off);
                }
            }
#pragma unroll
            for (int mi = 0; mi < 4; mi++)
#pragma unroll
                for (int nj = 0; nj < 4; nj++) {
                    mma_bf16(acc[mi][nj], afh[mi], bfh[nj]);
                    mma_bf16(acc[mi][nj], afh[mi], bfl[nj]);
                    mma_bf16(acc[mi][nj], afl[mi], bfh[nj]);
                }
        }
        __syncthreads();
    }

    // ---- store ----
#pragma unroll
    for (int mi = 0; mi < 4; mi++) {
#pragma unroll
        for (int nj = 0; nj < 4; nj++) {
            int r = row0 + wm + mi * 16 + (lane >> 2);
            int c = col0 + wn + nj * 8 + (lane & 3) * 2;
            float* p0 = C + (long long)r * ldc + c;
            p0[0] = acc[mi][nj][0] * alpha;
            p0[1] = acc[mi][nj][1] * alpha;
            float* p1 = C + (long long)(r + 8) * ldc + c;
            p1[0] = acc[mi][nj][2] * alpha;
            p1[1] = acc[mi][nj][3] * alpha;
        }
    }
}

// ---------------------------------------------------------------------------
// RoPE (in-place on g_q, g_k), start_pos = 0
// ---------------------------------------------------------------------------
__global__ void rope_v2() {
    long long idx = (long long)blockIdx.x * blockDim.x + threadIdx.x;
    const long long QP = (long long)S_LEN * HQ * 64;
    const long long KP = (long long)S_LEN * HKV * 64;
    if (idx >= QP + KP) return;

    float* base; int s, h, i, stride;
    if (idx < QP) {
        s = (int)(idx / (HQ * 64));
        int rem = (int)(idx % (HQ * 64));
        h = rem / 64; i = rem % 64;
        base = g_q; stride = DMODEL;
    } else {
        long long t = idx - QP;
        s = (int)(t / (HKV * 64));
        int rem = (int)(t % (HKV * 64));
        h = rem / 64; i = rem % 64;
        base = g_k; stride = DKV;
    }

    float invf = (float)(1.0 / pow(10000.0, (double)i / 64.0));
    float ang = (float)s * invf;
    double sd, cd;
    sincos((double)ang, &sd, &cd);
    float c = (float)cd, sn = (float)sd;

    size_t off = (size_t)s * (size_t)stride + (size_t)h * HD + 2 * (size_t)i;
    float x1 = base[off], x2 = base[off + 1];
    base[off]     = x1 * c  - x2 * sn;
    base[off + 1] = x1 * sn + x2 * c;
}

// ---------------------------------------------------------------------------
// Transpose V [s][d] -> Vt [d][s]
// ---------------------------------------------------------------------------
__global__ void transpose_v() {
    __shared__ float t[32][33];
    int d0 = blockIdx.x * 32;
    int s0 = blockIdx.y * 32;
    for (int i = threadIdx.y; i < 32; i += 8)
        t[i][threadIdx.x] = g_v[(size_t)(s0 + i) * DKV + d0 + threadIdx.x];
    __syncthreads();
    for (int i = threadIdx.y; i < 32; i += 8)
        g_vt[(size_t)(d0 + i) * S_LEN + s0 + threadIdx.x] = t[threadIdx.x][i];
}

// ---------------------------------------------------------------------------
// Softmax: one warp per row of 2048
// ---------------------------------------------------------------------------
__global__ __launch_bounds__(256) void softmax_v2() {
    const int row = blockIdx.x * 8 + (threadIdx.x >> 5);
    const int l   = threadIdx.x & 31;
    float* p = g_scores + (size_t)row * S_LEN;

    float vals[64];
    float m = -3.0e38f;
#pragma unroll
    for (int i = 0; i < 64; i++) {
        vals[i] = p[l + 32 * i];
        m = fmaxf(m, vals[i]);
    }
#pragma unroll
    for (int o = 16; o > 0; o >>= 1)
        m = fmaxf(m, __shfl_xor_sync(0xffffffffu, m, o));

    float s = 0.f;
#pragma unroll
    for (int i = 0; i < 64; i++) {
        vals[i] = expf(vals[i] - m);
        s += vals[i];
    }
#pragma unroll
    for (int o = 16; o > 0; o >>= 1)
        s += __shfl_xor_sync(0xffffffffu, s, o);

    float inv = 1.0f / s;
#pragma unroll
    for (int i = 0; i < 64; i++)
        p[l + 32 * i] = vals[i] * inv;
}

// ---------------------------------------------------------------------------
// Launch
// ---------------------------------------------------------------------------
extern "C" void kernel_launch(void* const* d_in, const int* in_sizes, int n_in,
                              void* d_out, int out_size)
{
    const float* x  = (const float*)d_in[0];
    const float* wq = (const float*)d_in[1];
    const float* wk = (const float*)d_in[2];
    const float* wv = (const float*)d_in[3];
    const float* wo = (const float*)d_in[4];
    float* out = (float*)d_out;

    float *q, *k, *v, *vt, *attn, *sc;
    cudaGetSymbolAddress((void**)&q,    g_q);
    cudaGetSymbolAddress((void**)&k,    g_k);
    cudaGetSymbolAddress((void**)&v,    g_v);
    cudaGetSymbolAddress((void**)&vt,   g_vt);
    cudaGetSymbolAddress((void**)&attn, g_attn);
    cudaGetSymbolAddress((void**)&sc,   g_scores);

    const float scale = 0.08838834764831845f;  // 1/sqrt(128)

    // 1) Projections
    tc_gemm_nt<<<dim3(DMODEL / 128, S_LEN / 128, 1), 256>>>(
        x, wq, q, S_LEN, DMODEL, DMODEL, DMODEL, DMODEL, DMODEL, 0, 0, 0, 1, 1.0f);
    tc_gemm_nt<<<dim3(DKV / 128, S_LEN / 128, 1), 256>>>(
        x, wk, k, S_LEN, DKV, DMODEL, DMODEL, DMODEL, DKV, 0, 0, 0, 1, 1.0f);
    tc_gemm_nt<<<dim3(DKV / 128, S_LEN / 128, 1), 256>>>(
        x, wv, v, S_LEN, DKV, DMODEL, DMODEL, DMODEL, DKV, 0, 0, 0, 1, 1.0f);

    // 2) RoPE on Q, K
    {
        long long total = (long long)S_LEN * HQ * 64 + (long long)S_LEN * HKV * 64;
        rope_v2<<<(int)((total + 255) / 256), 256>>>();
    }

    // 3) V transpose -> Vt[d][s]
    transpose_v<<<dim3(DKV / 32, S_LEN / 32), dim3(32, 8)>>>();

    // 4) scores[h] = scale * Q_h * K_{h/4}^T
    tc_gemm_nt<<<dim3(S_LEN / 128, S_LEN / 128, HQ), 256>>>(
        q, k, sc, S_LEN, S_LEN, HD, DMODEL, DKV, S_LEN,
        /*strA=*/HD, /*strB=*/HD, /*strC=*/(long long)S_LEN * S_LEN,
        /*bdivB=*/4, scale);

    // 5) softmax rows
    softmax_v2<<<(HQ * S_LEN) / 8, 256>>>();

    // 6) attn[h] = P_h * Vt_{h/4}^T  (NT with Vt: C[q,d] = sum_s P[q,s]*Vt[d,s])
    tc_gemm_nt<<<dim3(HD / 128, S_LEN / 128, HQ), 256>>>(
        sc, vt, attn, S_LEN, HD, S_LEN, S_LEN, S_LEN, DMODEL,
        /*strA=*/(long long)S_LEN * S_LEN, /*strB=*/(long long)HD * S_LEN,
        /*strC=*/HD, /*bdivB=*/4, 1.0f);

    // 7) out = attn * wo^T
    tc_gemm_nt<<<dim3(DMODEL / 128, S_LEN / 128, 1), 256>>>(
        attn, wo, out, S_LEN, DMODEL, DMODEL, DMODEL, DMODEL, DMODEL,
        0, 0, 0, 1, 1.0f);
}